// round 2
// baseline (speedup 1.0000x reference)
#include <cuda_runtime.h>
#include <cstdint>

// ---------------------------------------------------------------------------
// Problem constants
// ---------------------------------------------------------------------------
#define BATCH   4
#define TLEN    2048
#define BT      8192          // BATCH*TLEN
#define GDIM    4
#define HID     1024
#define NHEADS  16
#define DHEAD   64
#define EMB     1024          // NHEADS*DHEAD
#define CCH     4096          // GDIM*HID
#define KS      4
#define DIL     3

// ---------------------------------------------------------------------------
// Compile-time computation of per-head vocab offsets (prime search, mirrors
// the python reference exactly).
// ---------------------------------------------------------------------------
constexpr bool c_isprime(long long n) {
    if (n < 2) return false;
    if (n % 2 == 0) return n == 2;
    for (long long i = 3; i * i <= n; i += 2)
        if (n % i == 0) return false;
    return true;
}

struct OffT { long long off[16]; };

constexpr OffT make_off() {
    long long sizes[16] = {};
    int idx = 0;
    for (int ng = 0; ng < 2; ng++) {
        long long start = 129280 - 1;
        for (int h = 0; h < 8; h++) {
            long long c = start + 1;
            for (;;) {
                bool ok = c_isprime(c);
                if (ok) {
                    for (int j = 0; j < idx; j++)
                        if (sizes[j] == c) { ok = false; break; }
                }
                if (ok) break;
                ++c;
            }
            sizes[idx++] = c;
            start = c;
        }
    }
    OffT o{};
    long long acc = 0;
    for (int i = 0; i < 16; i++) { o.off[i] = acc; acc += sizes[i]; }
    return o;
}

constexpr OffT HOFF = make_off();

__constant__ long long d_off[16] = {
    HOFF.off[0],  HOFF.off[1],  HOFF.off[2],  HOFF.off[3],
    HOFF.off[4],  HOFF.off[5],  HOFF.off[6],  HOFF.off[7],
    HOFF.off[8],  HOFF.off[9],  HOFF.off[10], HOFF.off[11],
    HOFF.off[12], HOFF.off[13], HOFF.off[14], HOFF.off[15]
};

// ---------------------------------------------------------------------------
// Scratch (device globals; no allocation allowed)
// ---------------------------------------------------------------------------
__device__ float g_embs [(size_t)BT * EMB];          //  32 MB
__device__ float g_xn   [(size_t)BT * GDIM * HID];   // 128 MB
__device__ float g_value[(size_t)BT * EMB];          //  32 MB
__device__ float g_keys [(size_t)BT * GDIM * HID];   // 128 MB

// ---------------------------------------------------------------------------
// Reduction helpers
// ---------------------------------------------------------------------------
__device__ __forceinline__ float block_reduce_sum(float v) {
    #pragma unroll
    for (int o = 16; o; o >>= 1) v += __shfl_xor_sync(0xffffffffu, v, o);
    __shared__ float s[8];
    int w = threadIdx.x >> 5, l = threadIdx.x & 31;
    if (l == 0) s[w] = v;
    __syncthreads();
    if (w == 0) {
        v = (l < 8) ? s[l] : 0.f;
        #pragma unroll
        for (int o = 4; o; o >>= 1) v += __shfl_xor_sync(0xffffffffu, v, o);
        if (l == 0) s[0] = v;
    }
    __syncthreads();
    return s[0];
}

__device__ __forceinline__ float3 block_reduce3(float a, float b, float c) {
    #pragma unroll
    for (int o = 16; o; o >>= 1) {
        a += __shfl_xor_sync(0xffffffffu, a, o);
        b += __shfl_xor_sync(0xffffffffu, b, o);
        c += __shfl_xor_sync(0xffffffffu, c, o);
    }
    __shared__ float sa[8], sb[8], sc[8];
    int w = threadIdx.x >> 5, l = threadIdx.x & 31;
    if (l == 0) { sa[w] = a; sb[w] = b; sc[w] = c; }
    __syncthreads();
    if (w == 0) {
        a = (l < 8) ? sa[l] : 0.f;
        b = (l < 8) ? sb[l] : 0.f;
        c = (l < 8) ? sc[l] : 0.f;
        #pragma unroll
        for (int o = 4; o; o >>= 1) {
            a += __shfl_xor_sync(0xffffffffu, a, o);
            b += __shfl_xor_sync(0xffffffffu, b, o);
            c += __shfl_xor_sync(0xffffffffu, c, o);
        }
        if (l == 0) { sa[0] = a; sb[0] = b; sc[0] = c; }
    }
    __syncthreads();
    return make_float3(sa[0], sb[0], sc[0]);
}

// ---------------------------------------------------------------------------
// 1) Embedding gather: embs[bt, h*64+d] = table[hash[bt,h] + off[h]][d]
//    hash_ids are int32 on device (JAX downcasts int64 without x64 mode).
//    grid = BT, block = 256 (16 heads x 16 float4)
// ---------------------------------------------------------------------------
__global__ void gather_k(const int* __restrict__ hash,
                         const float* __restrict__ tab,
                         float* __restrict__ embs) {
    int bt = blockIdx.x;
    int tid = threadIdx.x;
    int h = tid >> 4;
    int q = tid & 15;
    long long row = (long long)hash[(size_t)bt * NHEADS + h] + d_off[h];
    float4 v = *(const float4*)&tab[row * DHEAD + q * 4];
    *(float4*)&embs[(size_t)bt * EMB + h * DHEAD + q * 4] = v;
}

// ---------------------------------------------------------------------------
// 2) RMSNorm(hidden, sc_norm_w, eps=1e-5) -> xn
//    grid = BT*GDIM, block = 256 (4 floats each)
// ---------------------------------------------------------------------------
__global__ void rms_sc_k(const float* __restrict__ x,
                         const float* __restrict__ w,
                         float* __restrict__ xn) {
    int r = blockIdx.x;             // (b*T+t)*G+g
    int g = r & 3;
    int tid = threadIdx.x;
    float4 v = ((const float4*)(x + (size_t)r * HID))[tid];
    float ss = v.x*v.x + v.y*v.y + v.z*v.z + v.w*v.w;
    ss = block_reduce_sum(ss);
    float sc = rsqrtf(ss * (1.f / HID) + 1e-5f);
    float4 wv = ((const float4*)(w + (size_t)g * HID))[tid];
    float4 o;
    o.x = v.x * sc * wv.x;
    o.y = v.y * sc * wv.y;
    o.z = v.z * sc * wv.z;
    o.w = v.w * sc * wv.w;
    ((float4*)(xn + (size_t)r * HID))[tid] = o;
}

// ---------------------------------------------------------------------------
// 3) NT GEMM:  C[m,n] = sum_k A[m,k]*B[n,k] + bias[n]
//    A: M x 1024 row-major (embs), B: N x 1024 row-major (weights),
//    128x128 block tile, BK=16, 256 threads, 8x8 micro-tile.
// ---------------------------------------------------------------------------
__global__ __launch_bounds__(256, 2)
void gemm_nt_k(const float* __restrict__ A, const float* __restrict__ Bm,
               const float* __restrict__ bias, float* __restrict__ C,
               int ldc) {
    const int K = 1024;
    __shared__ float As[16][128];
    __shared__ float Bs[16][128];

    int bm = blockIdx.y * 128, bn = blockIdx.x * 128;
    int tid = threadIdx.x;
    int tm = (tid >> 4) * 8;
    int tn = (tid & 15) * 8;
    int lr = tid >> 2;        // 0..63
    int lk = (tid & 3) * 4;   // 0,4,8,12

    float acc[8][8];
    #pragma unroll
    for (int i = 0; i < 8; i++)
        #pragma unroll
        for (int j = 0; j < 8; j++) acc[i][j] = 0.f;

    const float* Aptr = A  + (size_t)(bm + lr) * K + lk;
    const float* Bptr = Bm + (size_t)(bn + lr) * K + lk;

    for (int k0 = 0; k0 < K; k0 += 16) {
        float4 a0 = *(const float4*)(Aptr);
        float4 a1 = *(const float4*)(Aptr + (size_t)64 * K);
        float4 b0 = *(const float4*)(Bptr);
        float4 b1 = *(const float4*)(Bptr + (size_t)64 * K);

        As[lk+0][lr]    = a0.x; As[lk+1][lr]    = a0.y; As[lk+2][lr]    = a0.z; As[lk+3][lr]    = a0.w;
        As[lk+0][lr+64] = a1.x; As[lk+1][lr+64] = a1.y; As[lk+2][lr+64] = a1.z; As[lk+3][lr+64] = a1.w;
        Bs[lk+0][lr]    = b0.x; Bs[lk+1][lr]    = b0.y; Bs[lk+2][lr]    = b0.z; Bs[lk+3][lr]    = b0.w;
        Bs[lk+0][lr+64] = b1.x; Bs[lk+1][lr+64] = b1.y; Bs[lk+2][lr+64] = b1.z; Bs[lk+3][lr+64] = b1.w;
        __syncthreads();

        #pragma unroll
        for (int k = 0; k < 16; k++) {
            float a[8], b[8];
            *(float4*)(a)     = *(const float4*)&As[k][tm];
            *(float4*)(a + 4) = *(const float4*)&As[k][tm + 4];
            *(float4*)(b)     = *(const float4*)&Bs[k][tn];
            *(float4*)(b + 4) = *(const float4*)&Bs[k][tn + 4];
            #pragma unroll
            for (int i = 0; i < 8; i++)
                #pragma unroll
                for (int j = 0; j < 8; j++)
                    acc[i][j] = fmaf(a[i], b[j], acc[i][j]);
        }
        __syncthreads();
        Aptr += 16; Bptr += 16;
    }

    #pragma unroll
    for (int i = 0; i < 8; i++) {
        #pragma unroll
        for (int j = 0; j < 8; j += 4) {
            float4 o;
            o.x = acc[i][j+0] + bias[bn + tn + j + 0];
            o.y = acc[i][j+1] + bias[bn + tn + j + 1];
            o.z = acc[i][j+2] + bias[bn + tn + j + 2];
            o.w = acc[i][j+3] + bias[bn + tn + j + 3];
            *(float4*)&C[(size_t)(bm + tm + i) * ldc + bn + tn + j] = o;
        }
    }
}

// ---------------------------------------------------------------------------
// 4) Fused epilogue per (b,t,g):
//    conv(dilated causal, depthwise) on xn -> silu -> rms(q) ;
//    rms(keys) ; gate = sigmoid(dot(q,k)/32) ; out = gate * value
//    grid = BT*GDIM, block = 256 (4 channels each)
// ---------------------------------------------------------------------------
__global__ void final_k(const float* __restrict__ xn,
                        const float* __restrict__ convw,
                        const float* __restrict__ keys,
                        const float* __restrict__ value,
                        const float* __restrict__ n1w,
                        const float* __restrict__ n2w,
                        float* __restrict__ out) {
    int r = blockIdx.x;            // (b*T+t)*G + g
    int g = r & 3;
    int bt = r >> 2;               // b*T + t
    int t = bt & (TLEN - 1);
    int tid = threadIdx.x;
    int d = tid * 4;

    // taps: w[ch][k], ch = g*1024 + d + j
    const float4* wb = (const float4*)(convw + (size_t)(g * HID + d) * KS);
    float4 w0 = wb[0], w1 = wb[1], w2 = wb[2], w3 = wb[3];

    float y0 = 0.f, y1 = 0.f, y2 = 0.f, y3 = 0.f;
    #pragma unroll
    for (int k = 0; k < KS; k++) {
        int tp = t - (KS - 1 - k) * DIL;     // t-9, t-6, t-3, t
        if (tp >= 0) {
            size_t row = ((size_t)(bt - (KS - 1 - k) * DIL) * GDIM + g);
            float4 x = *(const float4*)&xn[row * HID + d];
            float wk0 = ((const float*)&w0)[k];
            float wk1 = ((const float*)&w1)[k];
            float wk2 = ((const float*)&w2)[k];
            float wk3 = ((const float*)&w3)[k];
            y0 = fmaf(x.x, wk0, y0);
            y1 = fmaf(x.y, wk1, y1);
            y2 = fmaf(x.z, wk2, y2);
            y3 = fmaf(x.w, wk3, y3);
        }
    }
    // silu
    float s0 = y0 / (1.f + __expf(-y0));
    float s1 = y1 / (1.f + __expf(-y1));
    float s2 = y2 / (1.f + __expf(-y2));
    float s3 = y3 / (1.f + __expf(-y3));

    float4 kv = *(const float4*)&keys[(size_t)bt * CCH + g * HID + d];
    float4 n1 = *(const float4*)&n1w[(size_t)g * HID + d];
    float4 n2 = *(const float4*)&n2w[(size_t)g * HID + d];

    float ssq = s0*s0 + s1*s1 + s2*s2 + s3*s3;
    float ksq = kv.x*kv.x + kv.y*kv.y + kv.z*kv.z + kv.w*kv.w;
    float dot = s0 * kv.x * n1.x * n2.x
              + s1 * kv.y * n1.y * n2.y
              + s2 * kv.z * n1.z * n2.z
              + s3 * kv.w * n1.w * n2.w;

    float3 red = block_reduce3(ssq, ksq, dot);

    float rq = rsqrtf(red.x * (1.f / HID) + 1e-6f);
    float rk = rsqrtf(red.y * (1.f / HID) + 1e-6f);
    float z  = red.z * rq * rk * (1.f / 32.f);   // sqrt(1024) = 32
    float gate = 1.f / (1.f + __expf(-z));

    float4 vv = *(const float4*)&value[(size_t)bt * EMB + d];
    float4 o;
    o.x = gate * vv.x;
    o.y = gate * vv.y;
    o.z = gate * vv.z;
    o.w = gate * vv.w;
    *(float4*)&out[(size_t)r * HID + d] = o;
}

// ---------------------------------------------------------------------------
// Launch
// ---------------------------------------------------------------------------
extern "C" void kernel_launch(void* const* d_in, const int* in_sizes, int n_in,
                              void* d_out, int out_size) {
    const float* hidden = (const float*)d_in[0];
    const int*   hash   = (const int*)d_in[1];
    const float* tab    = (const float*)d_in[2];
    const float* convw  = (const float*)d_in[3];
    const float* scw    = (const float*)d_in[4];
    const float* vw     = (const float*)d_in[5];
    const float* vb     = (const float*)d_in[6];
    const float* kw     = (const float*)d_in[7];
    const float* kb     = (const float*)d_in[8];
    const float* n1     = (const float*)d_in[9];
    const float* n2     = (const float*)d_in[10];
    float* out = (float*)d_out;

    float* embs;  cudaGetSymbolAddress((void**)&embs,  g_embs);
    float* xn;    cudaGetSymbolAddress((void**)&xn,    g_xn);
    float* val;   cudaGetSymbolAddress((void**)&val,   g_value);
    float* keys;  cudaGetSymbolAddress((void**)&keys,  g_keys);

    gather_k<<<BT, 256>>>(hash, tab, embs);
    rms_sc_k<<<BT * GDIM, 256>>>(hidden, scw, xn);

    dim3 gv(EMB / 128, BT / 128);          // value: N=1024
    gemm_nt_k<<<gv, 256>>>(embs, vw, vb, val, EMB);

    dim3 gk(CCH / 128, BT / 128);          // keys: N=4096
    gemm_nt_k<<<gk, 256>>>(embs, kw, kb, keys, CCH);

    final_k<<<BT * GDIM, 256>>>(xn, convw, keys, val, n1, n2, out);
}

// round 4
// speedup vs baseline: 2.0145x; 2.0145x over previous
#include <cuda_runtime.h>
#include <cuda_bf16.h>
#include <cstdint>

// ---------------------------------------------------------------------------
// Problem constants
// ---------------------------------------------------------------------------
#define BATCH   4
#define TLEN    2048
#define BT      8192
#define GDIM    4
#define HID     1024
#define NHEADS  16
#define DHEAD   64
#define EMB     1024
#define CCH     4096
#define KS      4
#define DIL     3

// ---------------------------------------------------------------------------
// Compile-time per-head vocab offsets (prime search; mirrors reference)
// ---------------------------------------------------------------------------
constexpr bool c_isprime(long long n) {
    if (n < 2) return false;
    if (n % 2 == 0) return n == 2;
    for (long long i = 3; i * i <= n; i += 2)
        if (n % i == 0) return false;
    return true;
}
struct OffT { long long off[16]; };
constexpr OffT make_off() {
    long long sizes[16] = {};
    int idx = 0;
    for (int ng = 0; ng < 2; ng++) {
        long long start = 129280 - 1;
        for (int h = 0; h < 8; h++) {
            long long c = start + 1;
            for (;;) {
                bool ok = c_isprime(c);
                if (ok) for (int j = 0; j < idx; j++) if (sizes[j] == c) { ok = false; break; }
                if (ok) break;
                ++c;
            }
            sizes[idx++] = c;
            start = c;
        }
    }
    OffT o{};
    long long acc = 0;
    for (int i = 0; i < 16; i++) { o.off[i] = acc; acc += sizes[i]; }
    return o;
}
constexpr OffT HOFF = make_off();
__constant__ long long d_off[16] = {
    HOFF.off[0], HOFF.off[1], HOFF.off[2], HOFF.off[3],
    HOFF.off[4], HOFF.off[5], HOFF.off[6], HOFF.off[7],
    HOFF.off[8], HOFF.off[9], HOFF.off[10], HOFF.off[11],
    HOFF.off[12], HOFF.off[13], HOFF.off[14], HOFF.off[15]
};

// ---------------------------------------------------------------------------
// Scratch (device globals)
// ---------------------------------------------------------------------------
__device__ float          g_xn   [(size_t)BT * CCH];     // 128 MB
__device__ float          g_value[(size_t)BT * EMB];     //  32 MB
__device__ float          g_keys [(size_t)BT * CCH];     // 128 MB
__device__ __nv_bfloat16  g_Ah   [(size_t)BT * EMB];     //  16 MB
__device__ __nv_bfloat16  g_Al   [(size_t)BT * EMB];     //  16 MB
__device__ __nv_bfloat16  g_vwh  [(size_t)EMB * HID];    //   2 MB
__device__ __nv_bfloat16  g_vwl  [(size_t)EMB * HID];
__device__ __nv_bfloat16  g_kwh  [(size_t)CCH * HID];    //   8 MB
__device__ __nv_bfloat16  g_kwl  [(size_t)CCH * HID];

// ---------------------------------------------------------------------------
// PTX helpers (sm_80-era: cp.async, ldmatrix, mma.sync — valid on compute_103)
// ---------------------------------------------------------------------------
__device__ __forceinline__ uint32_t smem_u32(const void* p) {
    uint32_t a;
    asm("{ .reg .u64 t; cvta.to.shared.u64 t, %1; cvt.u32.u64 %0, t; }" : "=r"(a) : "l"(p));
    return a;
}

#define CP16(sm, gm) asm volatile("cp.async.ca.shared.global [%0], [%1], 16;" :: "r"(sm), "l"(gm))
#define CPCOMMIT()   asm volatile("cp.async.commit_group;" ::: "memory")
#define CPWAIT(n)    asm volatile("cp.async.wait_group %0;" :: "n"(n) : "memory")

#define LDSM4(r0, r1, r2, r3, a)                                           \
    asm volatile("ldmatrix.sync.aligned.m8n8.x4.shared.b16 {%0,%1,%2,%3}, [%4];" \
        : "=r"(r0), "=r"(r1), "=r"(r2), "=r"(r3) : "r"(a))

#define MMA16816(d, a, b0, b1)                                             \
    asm volatile("mma.sync.aligned.m16n8k16.row.col.f32.bf16.bf16.f32 "    \
        "{%0,%1,%2,%3}, {%4,%5,%6,%7}, {%8,%9}, {%0,%1,%2,%3};"            \
        : "+f"((d)[0]), "+f"((d)[1]), "+f"((d)[2]), "+f"((d)[3])           \
        : "r"((a)[0]), "r"((a)[1]), "r"((a)[2]), "r"((a)[3]),              \
          "r"(b0), "r"(b1))

// XOR swizzle for [row][32 bf16] tiles (64B rows, 4x16B chunks).
// Conflict-free for cp.async 16B stores and ldmatrix.x4 8-row phases.
__device__ __forceinline__ uint32_t sofs(int row, int chunk) {
    int p = chunk ^ (row & 3) ^ ((row >> 2) & 1);
    return (uint32_t)(row * 64 + p * 16);
}

// ---------------------------------------------------------------------------
// Split-bf16 NT GEMM via mma.sync:
//   C[m,n] = sum_k A[m,k]*B[n,k] + bias[n],  A,B as bf16 hi/lo splits.
//   3 phases (AhBh, AlBh, AhBl) x 32 chunks of BK=32 = 96 stages, K=1024 each.
//   Tile 128x128, 8 warps (2x4), warp tile 64x32, cp.async double buffer.
// ---------------------------------------------------------------------------
__global__ __launch_bounds__(256, 2)
void gemm_mma(const __nv_bfloat16* __restrict__ Ah, const __nv_bfloat16* __restrict__ Al,
              const __nv_bfloat16* __restrict__ Bh, const __nv_bfloat16* __restrict__ Bl,
              const float* __restrict__ bias, float* __restrict__ C, int ldc) {
    __shared__ __align__(128) char As[2][128 * 64];
    __shared__ __align__(128) char Bs[2][128 * 64];

    const int tid = threadIdx.x;
    const int lane = tid & 31, wid = tid >> 5;
    const int wm = wid >> 2, wn = wid & 3;          // warp grid 2x4
    const int bm = blockIdx.y * 128, bn = blockIdx.x * 128;

    const int lr = tid >> 2;   // 0..63 (load row, +64 second iter)
    const int lc = tid & 3;    // 16B chunk

    const uint32_t aB0 = smem_u32(As[0]), aB1 = smem_u32(As[1]);
    const uint32_t bB0 = smem_u32(Bs[0]), bB1 = smem_u32(Bs[1]);

    float acc[4][4][4];
    #pragma unroll
    for (int i = 0; i < 4; i++)
        #pragma unroll
        for (int j = 0; j < 4; j++)
            #pragma unroll
            for (int q = 0; q < 4; q++) acc[i][j][q] = 0.f;

    const int NSTAGE = 96;

    // stage loader: phase p selects operand pair, kk = column offset in [0,1024)
    auto issue = [&](int s, int buf) {
        int p = s >> 5;
        int kk = (s & 31) * 32;
        const __nv_bfloat16* Ag = (p == 1) ? Al : Ah;
        const __nv_bfloat16* Bg = (p == 2) ? Bl : Bh;
        uint32_t ab = buf ? aB1 : aB0;
        uint32_t bb = buf ? bB1 : bB0;
        #pragma unroll
        for (int i = 0; i < 2; i++) {
            int row = lr + i * 64;
            CP16(ab + sofs(row, lc), Ag + (size_t)(bm + row) * 1024 + kk + lc * 8);
            CP16(bb + sofs(row, lc), Bg + (size_t)(bn + row) * 1024 + kk + lc * 8);
        }
        CPCOMMIT();
    };

    issue(0, 0);

    for (int s = 0; s < NSTAGE; s++) {
        int buf = s & 1;
        if (s + 1 < NSTAGE) {
            issue(s + 1, buf ^ 1);
            CPWAIT(1);
        } else {
            CPWAIT(0);
        }
        __syncthreads();

        uint32_t aB = buf ? aB1 : aB0;
        uint32_t bB = buf ? bB1 : bB0;

        #pragma unroll
        for (int ks = 0; ks < 32; ks += 16) {
            int colc = (ks + ((lane >> 4) << 3)) >> 3;   // chunk of this lane's k
            uint32_t afr[4][4];
            #pragma unroll
            for (int mi = 0; mi < 4; mi++) {
                int row = wm * 64 + mi * 16 + (lane & 15);
                LDSM4(afr[mi][0], afr[mi][1], afr[mi][2], afr[mi][3],
                      aB + sofs(row, colc));
            }
            uint32_t bfr[2][4];
            #pragma unroll
            for (int nj = 0; nj < 2; nj++) {
                int row = wn * 32 + nj * 16 + (lane & 7) + (((lane >> 3) & 1) << 3);
                LDSM4(bfr[nj][0], bfr[nj][1], bfr[nj][2], bfr[nj][3],
                      bB + sofs(row, colc));
            }
            #pragma unroll
            for (int mi = 0; mi < 4; mi++)
                #pragma unroll
                for (int nj2 = 0; nj2 < 4; nj2++) {
                    int nj = nj2 >> 1, hf = nj2 & 1;
                    MMA16816(acc[mi][nj2], afr[mi], bfr[nj][hf], bfr[nj][hf + 2]);
                }
        }
        __syncthreads();
    }

    // epilogue: C-fragment rows (lane>>2, +8), cols (lane&3)*2
    #pragma unroll
    for (int mi = 0; mi < 4; mi++) {
        int r0 = bm + wm * 64 + mi * 16 + (lane >> 2);
        #pragma unroll
        for (int nj2 = 0; nj2 < 4; nj2++) {
            int c = bn + wn * 32 + nj2 * 8 + (lane & 3) * 2;
            float2 bv = *(const float2*)&bias[c];
            float2 o0, o1;
            o0.x = acc[mi][nj2][0] + bv.x;
            o0.y = acc[mi][nj2][1] + bv.y;
            o1.x = acc[mi][nj2][2] + bv.x;
            o1.y = acc[mi][nj2][3] + bv.y;
            *(float2*)&C[(size_t)r0 * ldc + c]       = o0;
            *(float2*)&C[(size_t)(r0 + 8) * ldc + c] = o1;
        }
    }
}

// ---------------------------------------------------------------------------
// Embedding gather with bf16 hi/lo split (grid=BT, block=256)
// ---------------------------------------------------------------------------
__global__ void gather_split_k(const int* __restrict__ hash,
                               const float* __restrict__ tab,
                               __nv_bfloat16* __restrict__ Ah,
                               __nv_bfloat16* __restrict__ Al) {
    int bt = blockIdx.x;
    int tid = threadIdx.x;
    int h = tid >> 4;
    int q = tid & 15;
    long long row = (long long)hash[(size_t)bt * NHEADS + h] + d_off[h];
    float4 v = *(const float4*)&tab[row * DHEAD + q * 4];
    __nv_bfloat16 h0 = __float2bfloat16(v.x), h1 = __float2bfloat16(v.y);
    __nv_bfloat16 h2 = __float2bfloat16(v.z), h3 = __float2bfloat16(v.w);
    __nv_bfloat16 l0 = __float2bfloat16(v.x - __bfloat162float(h0));
    __nv_bfloat16 l1 = __float2bfloat16(v.y - __bfloat162float(h1));
    __nv_bfloat16 l2 = __float2bfloat16(v.z - __bfloat162float(h2));
    __nv_bfloat16 l3 = __float2bfloat16(v.w - __bfloat162float(h3));
    size_t o = (size_t)bt * EMB + h * DHEAD + q * 4;
    *(__nv_bfloat162*)&Ah[o]     = __nv_bfloat162(h0, h1);
    *(__nv_bfloat162*)&Ah[o + 2] = __nv_bfloat162(h2, h3);
    *(__nv_bfloat162*)&Al[o]     = __nv_bfloat162(l0, l1);
    *(__nv_bfloat162*)&Al[o + 2] = __nv_bfloat162(l2, l3);
}

// ---------------------------------------------------------------------------
// Weight hi/lo split (n4 float4 elements)
// ---------------------------------------------------------------------------
__global__ void wsplit_k(const float* __restrict__ w,
                         __nv_bfloat16* __restrict__ hi,
                         __nv_bfloat16* __restrict__ lo, int n4) {
    int i = blockIdx.x * blockDim.x + threadIdx.x;
    if (i >= n4) return;
    float4 v = ((const float4*)w)[i];
    __nv_bfloat16 h0 = __float2bfloat16(v.x), h1 = __float2bfloat16(v.y);
    __nv_bfloat16 h2 = __float2bfloat16(v.z), h3 = __float2bfloat16(v.w);
    __nv_bfloat16 l0 = __float2bfloat16(v.x - __bfloat162float(h0));
    __nv_bfloat16 l1 = __float2bfloat16(v.y - __bfloat162float(h1));
    __nv_bfloat16 l2 = __float2bfloat16(v.z - __bfloat162float(h2));
    __nv_bfloat16 l3 = __float2bfloat16(v.w - __bfloat162float(h3));
    size_t o = (size_t)i * 4;
    *(__nv_bfloat162*)&hi[o]     = __nv_bfloat162(h0, h1);
    *(__nv_bfloat162*)&hi[o + 2] = __nv_bfloat162(h2, h3);
    *(__nv_bfloat162*)&lo[o]     = __nv_bfloat162(l0, l1);
    *(__nv_bfloat162*)&lo[o + 2] = __nv_bfloat162(l2, l3);
}

// ---------------------------------------------------------------------------
// RMSNorm(hidden, sc_norm_w, eps=1e-5) -> xn
// ---------------------------------------------------------------------------
__device__ __forceinline__ float block_reduce_sum(float v) {
    #pragma unroll
    for (int o = 16; o; o >>= 1) v += __shfl_xor_sync(0xffffffffu, v, o);
    __shared__ float s[8];
    int w = threadIdx.x >> 5, l = threadIdx.x & 31;
    if (l == 0) s[w] = v;
    __syncthreads();
    if (w == 0) {
        v = (l < 8) ? s[l] : 0.f;
        #pragma unroll
        for (int o = 4; o; o >>= 1) v += __shfl_xor_sync(0xffffffffu, v, o);
        if (l == 0) s[0] = v;
    }
    __syncthreads();
    return s[0];
}

__global__ void rms_sc_k(const float* __restrict__ x,
                         const float* __restrict__ w,
                         float* __restrict__ xn) {
    int r = blockIdx.x;
    int g = r & 3;
    int tid = threadIdx.x;
    float4 v = ((const float4*)(x + (size_t)r * HID))[tid];
    float ss = v.x*v.x + v.y*v.y + v.z*v.z + v.w*v.w;
    ss = block_reduce_sum(ss);
    float sc = rsqrtf(ss * (1.f / HID) + 1e-5f);
    float4 wv = ((const float4*)(w + (size_t)g * HID))[tid];
    float4 o;
    o.x = v.x * sc * wv.x; o.y = v.y * sc * wv.y;
    o.z = v.z * sc * wv.z; o.w = v.w * sc * wv.w;
    ((float4*)(xn + (size_t)r * HID))[tid] = o;
}

// ---------------------------------------------------------------------------
// Final fused kernel (conv -> silu -> q-rms ; k-rms ; gate ; out)
// ---------------------------------------------------------------------------
__device__ __forceinline__ float3 block_reduce3(float a, float b, float c) {
    #pragma unroll
    for (int o = 16; o; o >>= 1) {
        a += __shfl_xor_sync(0xffffffffu, a, o);
        b += __shfl_xor_sync(0xffffffffu, b, o);
        c += __shfl_xor_sync(0xffffffffu, c, o);
    }
    __shared__ float sa[8], sb[8], sc[8];
    int w = threadIdx.x >> 5, l = threadIdx.x & 31;
    if (l == 0) { sa[w] = a; sb[w] = b; sc[w] = c; }
    __syncthreads();
    if (w == 0) {
        a = (l < 8) ? sa[l] : 0.f;
        b = (l < 8) ? sb[l] : 0.f;
        c = (l < 8) ? sc[l] : 0.f;
        #pragma unroll
        for (int o = 4; o; o >>= 1) {
            a += __shfl_xor_sync(0xffffffffu, a, o);
            b += __shfl_xor_sync(0xffffffffu, b, o);
            c += __shfl_xor_sync(0xffffffffu, c, o);
        }
        if (l == 0) { sa[0] = a; sb[0] = b; sc[0] = c; }
    }
    __syncthreads();
    return make_float3(sa[0], sb[0], sc[0]);
}

__global__ void final_k(const float* __restrict__ xn,
                        const float* __restrict__ convw,
                        const float* __restrict__ keys,
                        const float* __restrict__ value,
                        const float* __restrict__ n1w,
                        const float* __restrict__ n2w,
                        float* __restrict__ out) {
    int r = blockIdx.x;
    int g = r & 3;
    int bt = r >> 2;
    int t = bt & (TLEN - 1);
    int tid = threadIdx.x;
    int d = tid * 4;

    const float4* wb = (const float4*)(convw + (size_t)(g * HID + d) * KS);
    float4 w0 = wb[0], w1 = wb[1], w2 = wb[2], w3 = wb[3];

    float y0 = 0.f, y1 = 0.f, y2 = 0.f, y3 = 0.f;
    #pragma unroll
    for (int k = 0; k < KS; k++) {
        int tp = t - (KS - 1 - k) * DIL;
        if (tp >= 0) {
            size_t row = ((size_t)(bt - (KS - 1 - k) * DIL) * GDIM + g);
            float4 x = *(const float4*)&xn[row * HID + d];
            y0 = fmaf(x.x, ((const float*)&w0)[k], y0);
            y1 = fmaf(x.y, ((const float*)&w1)[k], y1);
            y2 = fmaf(x.z, ((const float*)&w2)[k], y2);
            y3 = fmaf(x.w, ((const float*)&w3)[k], y3);
        }
    }
    float s0 = y0 / (1.f + __expf(-y0));
    float s1 = y1 / (1.f + __expf(-y1));
    float s2 = y2 / (1.f + __expf(-y2));
    float s3 = y3 / (1.f + __expf(-y3));

    float4 kv = *(const float4*)&keys[(size_t)bt * CCH + g * HID + d];
    float4 n1 = *(const float4*)&n1w[(size_t)g * HID + d];
    float4 n2 = *(const float4*)&n2w[(size_t)g * HID + d];

    float ssq = s0*s0 + s1*s1 + s2*s2 + s3*s3;
    float ksq = kv.x*kv.x + kv.y*kv.y + kv.z*kv.z + kv.w*kv.w;
    float dot = s0*kv.x*n1.x*n2.x + s1*kv.y*n1.y*n2.y
              + s2*kv.z*n1.z*n2.z + s3*kv.w*n1.w*n2.w;

    float3 red = block_reduce3(ssq, ksq, dot);

    float rq = rsqrtf(red.x * (1.f / HID) + 1e-6f);
    float rk = rsqrtf(red.y * (1.f / HID) + 1e-6f);
    float z  = red.z * rq * rk * (1.f / 32.f);
    float gate = 1.f / (1.f + __expf(-z));

    float4 vv = *(const float4*)&value[(size_t)bt * EMB + d];
    float4 o;
    o.x = gate * vv.x; o.y = gate * vv.y;
    o.z = gate * vv.z; o.w = gate * vv.w;
    *(float4*)&out[(size_t)r * HID + d] = o;
}

// ---------------------------------------------------------------------------
// Launch
// ---------------------------------------------------------------------------
extern "C" void kernel_launch(void* const* d_in, const int* in_sizes, int n_in,
                              void* d_out, int out_size) {
    const float* hidden = (const float*)d_in[0];
    const int*   hash   = (const int*)d_in[1];
    const float* tab    = (const float*)d_in[2];
    const float* convw  = (const float*)d_in[3];
    const float* scw    = (const float*)d_in[4];
    const float* vw     = (const float*)d_in[5];
    const float* vb     = (const float*)d_in[6];
    const float* kw     = (const float*)d_in[7];
    const float* kb     = (const float*)d_in[8];
    const float* n1     = (const float*)d_in[9];
    const float* n2     = (const float*)d_in[10];
    float* out = (float*)d_out;

    float *xn, *val, *keys;
    __nv_bfloat16 *Ah, *Al, *vwh, *vwl, *kwh, *kwl;
    cudaGetSymbolAddress((void**)&xn,   g_xn);
    cudaGetSymbolAddress((void**)&val,  g_value);
    cudaGetSymbolAddress((void**)&keys, g_keys);
    cudaGetSymbolAddress((void**)&Ah,   g_Ah);
    cudaGetSymbolAddress((void**)&Al,   g_Al);
    cudaGetSymbolAddress((void**)&vwh,  g_vwh);
    cudaGetSymbolAddress((void**)&vwl,  g_vwl);
    cudaGetSymbolAddress((void**)&kwh,  g_kwh);
    cudaGetSymbolAddress((void**)&kwl,  g_kwl);

    gather_split_k<<<BT, 256>>>(hash, tab, Ah, Al);
    wsplit_k<<<(EMB * HID / 4 + 255) / 256, 256>>>(vw, vwh, vwl, EMB * HID / 4);
    wsplit_k<<<(CCH * HID / 4 + 255) / 256, 256>>>(kw, kwh, kwl, CCH * HID / 4);
    rms_sc_k<<<BT * GDIM, 256>>>(hidden, scw, xn);

    dim3 gv(EMB / 128, BT / 128);
    gemm_mma<<<gv, 256>>>(Ah, Al, vwh, vwl, vb, val, EMB);

    dim3 gk(CCH / 128, BT / 128);
    gemm_mma<<<gk, 256>>>(Ah, Al, kwh, kwl, kb, keys, CCH);

    final_k<<<BT * GDIM, 256>>>(xn, convw, keys, val, n1, n2, out);
}

// round 7
// speedup vs baseline: 2.2595x; 1.1216x over previous
#include <cuda_runtime.h>
#include <cuda_bf16.h>
#include <cstdint>

// ---------------------------------------------------------------------------
// Problem constants
// ---------------------------------------------------------------------------
#define BATCH   4
#define TLEN    2048
#define BT      8192
#define GDIM    4
#define HID     1024
#define NHEADS  16
#define DHEAD   64
#define EMB     1024
#define CCH     4096
#define KS      4
#define DIL     3

// ---------------------------------------------------------------------------
// Compile-time per-head vocab offsets (prime search; mirrors reference)
// ---------------------------------------------------------------------------
constexpr bool c_isprime(long long n) {
    if (n < 2) return false;
    if (n % 2 == 0) return n == 2;
    for (long long i = 3; i * i <= n; i += 2)
        if (n % i == 0) return false;
    return true;
}
struct OffT { long long off[16]; };
constexpr OffT make_off() {
    long long sizes[16] = {};
    int idx = 0;
    for (int ng = 0; ng < 2; ng++) {
        long long start = 129280 - 1;
        for (int h = 0; h < 8; h++) {
            long long c = start + 1;
            for (;;) {
                bool ok = c_isprime(c);
                if (ok) for (int j = 0; j < idx; j++) if (sizes[j] == c) { ok = false; break; }
                if (ok) break;
                ++c;
            }
            sizes[idx++] = c;
            start = c;
        }
    }
    OffT o{};
    long long acc = 0;
    for (int i = 0; i < 16; i++) { o.off[i] = acc; acc += sizes[i]; }
    return o;
}
constexpr OffT HOFF = make_off();
__constant__ long long d_off[16] = {
    HOFF.off[0], HOFF.off[1], HOFF.off[2], HOFF.off[3],
    HOFF.off[4], HOFF.off[5], HOFF.off[6], HOFF.off[7],
    HOFF.off[8], HOFF.off[9], HOFF.off[10], HOFF.off[11],
    HOFF.off[12], HOFF.off[13], HOFF.off[14], HOFF.off[15]
};

// ---------------------------------------------------------------------------
// Scratch (device globals)
// ---------------------------------------------------------------------------
__device__ float          g_xn   [(size_t)BT * CCH];     // 128 MB
__device__ float          g_value[(size_t)BT * EMB];     //  32 MB
__device__ float          g_keys [(size_t)BT * CCH];     // 128 MB
__device__ __nv_bfloat16  g_Ah   [(size_t)BT * EMB];     //  16 MB
__device__ __nv_bfloat16  g_Al   [(size_t)BT * EMB];     //  16 MB
__device__ __nv_bfloat16  g_vwh  [(size_t)EMB * HID];    //   2 MB
__device__ __nv_bfloat16  g_vwl  [(size_t)EMB * HID];
__device__ __nv_bfloat16  g_kwh  [(size_t)CCH * HID];    //   8 MB
__device__ __nv_bfloat16  g_kwl  [(size_t)CCH * HID];

// ---------------------------------------------------------------------------
// PTX helpers (sm_80-era: cp.async, ldmatrix, mma.sync — valid on compute_103)
// ---------------------------------------------------------------------------
__device__ __forceinline__ uint32_t smem_u32(const void* p) {
    uint32_t a;
    asm("{ .reg .u64 t; cvta.to.shared.u64 t, %1; cvt.u32.u64 %0, t; }" : "=r"(a) : "l"(p));
    return a;
}

#define CP16(sm, gm) asm volatile("cp.async.ca.shared.global [%0], [%1], 16;" :: "r"(sm), "l"(gm))
#define CPCOMMIT()   asm volatile("cp.async.commit_group;" ::: "memory")
#define CPWAIT(n)    asm volatile("cp.async.wait_group %0;" :: "n"(n) : "memory")

#define LDSM4(r0, r1, r2, r3, a)                                           \
    asm volatile("ldmatrix.sync.aligned.m8n8.x4.shared.b16 {%0,%1,%2,%3}, [%4];" \
        : "=r"(r0), "=r"(r1), "=r"(r2), "=r"(r3) : "r"(a))

#define MMA16816(d, a, b0, b1)                                             \
    asm volatile("mma.sync.aligned.m16n8k16.row.col.f32.bf16.bf16.f32 "    \
        "{%0,%1,%2,%3}, {%4,%5,%6,%7}, {%8,%9}, {%0,%1,%2,%3};"            \
        : "+f"((d)[0]), "+f"((d)[1]), "+f"((d)[2]), "+f"((d)[3])           \
        : "r"((a)[0]), "r"((a)[1]), "r"((a)[2]), "r"((a)[3]),              \
          "r"(b0), "r"(b1))

// XOR swizzle for [row][32 bf16] tiles (64B rows, 4x16B chunks).
__device__ __forceinline__ uint32_t sofs(int row, int chunk) {
    int p = chunk ^ (row & 3) ^ ((row >> 2) & 1);
    return (uint32_t)(row * 64 + p * 16);
}

// Tile byte offsets within one 32KB chunk buffer
#define T_AH 0
#define T_AL 8192
#define T_BH 16384
#define T_BL 24576
#define BUFSZ 32768
#define GEMM_SMEM (2 * BUFSZ)

// ---------------------------------------------------------------------------
// Split-bf16 NT GEMM via mma.sync, chunk-major:
//   C[m,n] = sum_k A[m,k]*B[n,k] + bias[n]
//   Per 32-wide K-chunk: load Ah,Al,Bh,Bl once; run 3 phases
//   (AhBh, AhBl, AlBh) reusing fragments.  Tile 128x128, 8 warps (2x4),
//   warp tile 64x32, cp.async double buffer, 32 stages.
// ---------------------------------------------------------------------------
__global__ __launch_bounds__(256, 2)
void gemm_mma(const __nv_bfloat16* __restrict__ Ah, const __nv_bfloat16* __restrict__ Al,
              const __nv_bfloat16* __restrict__ Bh, const __nv_bfloat16* __restrict__ Bl,
              const float* __restrict__ bias, float* __restrict__ C, int ldc) {
    extern __shared__ __align__(128) char smem[];
    const uint32_t sb = smem_u32(smem);

    const int tid = threadIdx.x;
    const int lane = tid & 31, wid = tid >> 5;
    const int wm = wid >> 2, wn = wid & 3;          // warp grid 2x4
    const int bm = blockIdx.y * 128, bn = blockIdx.x * 128;

    const int lr = tid >> 2;   // 0..63 (load row; +64 second iter)
    const int lc = tid & 3;    // 16B chunk

    float acc[4][4][4];
    #pragma unroll
    for (int i = 0; i < 4; i++)
        #pragma unroll
        for (int j = 0; j < 4; j++)
            #pragma unroll
            for (int q = 0; q < 4; q++) acc[i][j][q] = 0.f;

    // stage loader: one 32-wide K-chunk, all four operand tiles
    auto issue = [&](int kc, int buf) {
        int kk = kc * 32;
        uint32_t base = sb + buf * BUFSZ;
        #pragma unroll
        for (int i = 0; i < 2; i++) {
            int row = lr + i * 64;
            uint32_t so = sofs(row, lc);
            size_t ga = (size_t)(bm + row) * 1024 + kk + lc * 8;
            size_t gb = (size_t)(bn + row) * 1024 + kk + lc * 8;
            CP16(base + T_AH + so, Ah + ga);
            CP16(base + T_AL + so, Al + ga);
            CP16(base + T_BH + so, Bh + gb);
            CP16(base + T_BL + so, Bl + gb);
        }
        CPCOMMIT();
    };

    issue(0, 0);

    for (int kc = 0; kc < 32; kc++) {
        int buf = kc & 1;
        if (kc + 1 < 32) {
            issue(kc + 1, buf ^ 1);
            CPWAIT(1);
        } else {
            CPWAIT(0);
        }
        __syncthreads();

        uint32_t base = sb + buf * BUFSZ;

        #pragma unroll
        for (int ks = 0; ks < 32; ks += 16) {
            const int colc = (ks >> 3) + (lane >> 4);
            const int arow = wm * 64 + (lane & 15);
            const int brow = wn * 32 + (lane & 7) + (((lane >> 3) & 1) << 3);

            // -- phase 1: Ah x Bh --
            uint32_t ah[4][4];
            #pragma unroll
            for (int mi = 0; mi < 4; mi++)
                LDSM4(ah[mi][0], ah[mi][1], ah[mi][2], ah[mi][3],
                      base + T_AH + sofs(arow + mi * 16, colc));
            uint32_t bh[2][4];
            #pragma unroll
            for (int nj = 0; nj < 2; nj++)
                LDSM4(bh[nj][0], bh[nj][1], bh[nj][2], bh[nj][3],
                      base + T_BH + sofs(brow + nj * 16, colc));
            #pragma unroll
            for (int mi = 0; mi < 4; mi++)
                #pragma unroll
                for (int nj2 = 0; nj2 < 4; nj2++) {
                    int nj = nj2 >> 1, hf = nj2 & 1;
                    MMA16816(acc[mi][nj2], ah[mi], bh[nj][hf], bh[nj][hf + 2]);
                }

            // -- phase 2: Ah x Bl (Ah reused) --
            {
                uint32_t bl[2][4];
                #pragma unroll
                for (int nj = 0; nj < 2; nj++)
                    LDSM4(bl[nj][0], bl[nj][1], bl[nj][2], bl[nj][3],
                          base + T_BL + sofs(brow + nj * 16, colc));
                #pragma unroll
                for (int mi = 0; mi < 4; mi++)
                    #pragma unroll
                    for (int nj2 = 0; nj2 < 4; nj2++) {
                        int nj = nj2 >> 1, hf = nj2 & 1;
                        MMA16816(acc[mi][nj2], ah[mi], bl[nj][hf], bl[nj][hf + 2]);
                    }
            }

            // -- phase 3: Al x Bh (Bh reused) --
            {
                #pragma unroll
                for (int mi = 0; mi < 4; mi++) {
                    uint32_t al[4];
                    LDSM4(al[0], al[1], al[2], al[3],
                          base + T_AL + sofs(arow + mi * 16, colc));
                    #pragma unroll
                    for (int nj2 = 0; nj2 < 4; nj2++) {
                        int nj = nj2 >> 1, hf = nj2 & 1;
                        MMA16816(acc[mi][nj2], al, bh[nj][hf], bh[nj][hf + 2]);
                    }
                }
            }
        }
        __syncthreads();
    }

    // epilogue: C-fragment rows (lane>>2, +8), cols (lane&3)*2
    #pragma unroll
    for (int mi = 0; mi < 4; mi++) {
        int r0 = bm + wm * 64 + mi * 16 + (lane >> 2);
        #pragma unroll
        for (int nj2 = 0; nj2 < 4; nj2++) {
            int c = bn + wn * 32 + nj2 * 8 + (lane & 3) * 2;
            float2 bv = *(const float2*)&bias[c];
            float2 o0, o1;
            o0.x = acc[mi][nj2][0] + bv.x;
            o0.y = acc[mi][nj2][1] + bv.y;
            o1.x = acc[mi][nj2][2] + bv.x;
            o1.y = acc[mi][nj2][3] + bv.y;
            *(float2*)&C[(size_t)r0 * ldc + c]       = o0;
            *(float2*)&C[(size_t)(r0 + 8) * ldc + c] = o1;
        }
    }
}

// ---------------------------------------------------------------------------
// Embedding gather with bf16 hi/lo split (grid=BT, block=256)
// ---------------------------------------------------------------------------
__global__ void gather_split_k(const int* __restrict__ hash,
                               const float* __restrict__ tab,
                               __nv_bfloat16* __restrict__ Ah,
                               __nv_bfloat16* __restrict__ Al) {
    int bt = blockIdx.x;
    int tid = threadIdx.x;
    int h = tid >> 4;
    int q = tid & 15;
    long long row = (long long)hash[(size_t)bt * NHEADS + h] + d_off[h];
    float4 v = *(const float4*)&tab[row * DHEAD + q * 4];
    __nv_bfloat16 h0 = __float2bfloat16(v.x), h1 = __float2bfloat16(v.y);
    __nv_bfloat16 h2 = __float2bfloat16(v.z), h3 = __float2bfloat16(v.w);
    __nv_bfloat16 l0 = __float2bfloat16(v.x - __bfloat162float(h0));
    __nv_bfloat16 l1 = __float2bfloat16(v.y - __bfloat162float(h1));
    __nv_bfloat16 l2 = __float2bfloat16(v.z - __bfloat162float(h2));
    __nv_bfloat16 l3 = __float2bfloat16(v.w - __bfloat162float(h3));
    size_t o = (size_t)bt * EMB + h * DHEAD + q * 4;
    *(__nv_bfloat162*)&Ah[o]     = __nv_bfloat162(h0, h1);
    *(__nv_bfloat162*)&Ah[o + 2] = __nv_bfloat162(h2, h3);
    *(__nv_bfloat162*)&Al[o]     = __nv_bfloat162(l0, l1);
    *(__nv_bfloat162*)&Al[o + 2] = __nv_bfloat162(l2, l3);
}

// ---------------------------------------------------------------------------
// Weight hi/lo split (n4 float4 elements)
// ---------------------------------------------------------------------------
__global__ void wsplit_k(const float* __restrict__ w,
                         __nv_bfloat16* __restrict__ hi,
                         __nv_bfloat16* __restrict__ lo, int n4) {
    int i = blockIdx.x * blockDim.x + threadIdx.x;
    if (i >= n4) return;
    float4 v = ((const float4*)w)[i];
    __nv_bfloat16 h0 = __float2bfloat16(v.x), h1 = __float2bfloat16(v.y);
    __nv_bfloat16 h2 = __float2bfloat16(v.z), h3 = __float2bfloat16(v.w);
    __nv_bfloat16 l0 = __float2bfloat16(v.x - __bfloat162float(h0));
    __nv_bfloat16 l1 = __float2bfloat16(v.y - __bfloat162float(h1));
    __nv_bfloat16 l2 = __float2bfloat16(v.z - __bfloat162float(h2));
    __nv_bfloat16 l3 = __float2bfloat16(v.w - __bfloat162float(h3));
    size_t o = (size_t)i * 4;
    *(__nv_bfloat162*)&hi[o]     = __nv_bfloat162(h0, h1);
    *(__nv_bfloat162*)&hi[o + 2] = __nv_bfloat162(h2, h3);
    *(__nv_bfloat162*)&lo[o]     = __nv_bfloat162(l0, l1);
    *(__nv_bfloat162*)&lo[o + 2] = __nv_bfloat162(l2, l3);
}

// ---------------------------------------------------------------------------
// RMSNorm(hidden, sc_norm_w, eps=1e-5) -> xn
// ---------------------------------------------------------------------------
__device__ __forceinline__ float block_reduce_sum(float v) {
    #pragma unroll
    for (int o = 16; o; o >>= 1) v += __shfl_xor_sync(0xffffffffu, v, o);
    __shared__ float s[8];
    int w = threadIdx.x >> 5, l = threadIdx.x & 31;
    if (l == 0) s[w] = v;
    __syncthreads();
    if (w == 0) {
        v = (l < 8) ? s[l] : 0.f;
        #pragma unroll
        for (int o = 4; o; o >>= 1) v += __shfl_xor_sync(0xffffffffu, v, o);
        if (l == 0) s[0] = v;
    }
    __syncthreads();
    return s[0];
}

__global__ void rms_sc_k(const float* __restrict__ x,
                         const float* __restrict__ w,
                         float* __restrict__ xn) {
    int r = blockIdx.x;
    int g = r & 3;
    int tid = threadIdx.x;
    float4 v = ((const float4*)(x + (size_t)r * HID))[tid];
    float ss = v.x*v.x + v.y*v.y + v.z*v.z + v.w*v.w;
    ss = block_reduce_sum(ss);
    float sc = rsqrtf(ss * (1.f / HID) + 1e-5f);
    float4 wv = ((const float4*)(w + (size_t)g * HID))[tid];
    float4 o;
    o.x = v.x * sc * wv.x; o.y = v.y * sc * wv.y;
    o.z = v.z * sc * wv.z; o.w = v.w * sc * wv.w;
    ((float4*)(xn + (size_t)r * HID))[tid] = o;
}

// ---------------------------------------------------------------------------
// Final fused kernel (conv -> silu -> q-rms ; k-rms ; gate ; out)
// ---------------------------------------------------------------------------
__device__ __forceinline__ float3 block_reduce3(float a, float b, float c) {
    #pragma unroll
    for (int o = 16; o; o >>= 1) {
        a += __shfl_xor_sync(0xffffffffu, a, o);
        b += __shfl_xor_sync(0xffffffffu, b, o);
        c += __shfl_xor_sync(0xffffffffu, c, o);
    }
    __shared__ float sa[8], sb[8], sc[8];
    int w = threadIdx.x >> 5, l = threadIdx.x & 31;
    if (l == 0) { sa[w] = a; sb[w] = b; sc[w] = c; }
    __syncthreads();
    if (w == 0) {
        a = (l < 8) ? sa[l] : 0.f;
        b = (l < 8) ? sb[l] : 0.f;
        c = (l < 8) ? sc[l] : 0.f;
        #pragma unroll
        for (int o = 4; o; o >>= 1) {
            a += __shfl_xor_sync(0xffffffffu, a, o);
            b += __shfl_xor_sync(0xffffffffu, b, o);
            c += __shfl_xor_sync(0xffffffffu, c, o);
        }
        if (l == 0) { sa[0] = a; sb[0] = b; sc[0] = c; }
    }
    __syncthreads();
    return make_float3(sa[0], sb[0], sc[0]);
}

__global__ void final_k(const float* __restrict__ xn,
                        const float* __restrict__ convw,
                        const float* __restrict__ keys,
                        const float* __restrict__ value,
                        const float* __restrict__ n1w,
                        const float* __restrict__ n2w,
                        float* __restrict__ out) {
    int r = blockIdx.x;
    int g = r & 3;
    int bt = r >> 2;
    int t = bt & (TLEN - 1);
    int tid = threadIdx.x;
    int d = tid * 4;

    const float4* wb = (const float4*)(convw + (size_t)(g * HID + d) * KS);
    float4 w0 = wb[0], w1 = wb[1], w2 = wb[2], w3 = wb[3];

    float y0 = 0.f, y1 = 0.f, y2 = 0.f, y3 = 0.f;
    #pragma unroll
    for (int k = 0; k < KS; k++) {
        int tp = t - (KS - 1 - k) * DIL;
        if (tp >= 0) {
            size_t row = ((size_t)(bt - (KS - 1 - k) * DIL) * GDIM + g);
            float4 x = *(const float4*)&xn[row * HID + d];
            y0 = fmaf(x.x, ((const float*)&w0)[k], y0);
            y1 = fmaf(x.y, ((const float*)&w1)[k], y1);
            y2 = fmaf(x.z, ((const float*)&w2)[k], y2);
            y3 = fmaf(x.w, ((const float*)&w3)[k], y3);
        }
    }
    float s0 = y0 / (1.f + __expf(-y0));
    float s1 = y1 / (1.f + __expf(-y1));
    float s2 = y2 / (1.f + __expf(-y2));
    float s3 = y3 / (1.f + __expf(-y3));

    float4 kv = *(const float4*)&keys[(size_t)bt * CCH + g * HID + d];
    float4 n1 = *(const float4*)&n1w[(size_t)g * HID + d];
    float4 n2 = *(const float4*)&n2w[(size_t)g * HID + d];

    float ssq = s0*s0 + s1*s1 + s2*s2 + s3*s3;
    float ksq = kv.x*kv.x + kv.y*kv.y + kv.z*kv.z + kv.w*kv.w;
    float dot = s0*kv.x*n1.x*n2.x + s1*kv.y*n1.y*n2.y
              + s2*kv.z*n1.z*n2.z + s3*kv.w*n1.w*n2.w;

    float3 red = block_reduce3(ssq, ksq, dot);

    float rq = rsqrtf(red.x * (1.f / HID) + 1e-6f);
    float rk = rsqrtf(red.y * (1.f / HID) + 1e-6f);
    float z  = red.z * rq * rk * (1.f / 32.f);
    float gate = 1.f / (1.f + __expf(-z));

    float4 vv = *(const float4*)&value[(size_t)bt * EMB + d];
    float4 o;
    o.x = gate * vv.x; o.y = gate * vv.y;
    o.z = gate * vv.z; o.w = gate * vv.w;
    *(float4*)&out[(size_t)r * HID + d] = o;
}

// ---------------------------------------------------------------------------
// Launch
// ---------------------------------------------------------------------------
extern "C" void kernel_launch(void* const* d_in, const int* in_sizes, int n_in,
                              void* d_out, int out_size) {
    const float* hidden = (const float*)d_in[0];
    const int*   hash   = (const int*)d_in[1];
    const float* tab    = (const float*)d_in[2];
    const float* convw  = (const float*)d_in[3];
    const float* scw    = (const float*)d_in[4];
    const float* vw     = (const float*)d_in[5];
    const float* vb     = (const float*)d_in[6];
    const float* kw     = (const float*)d_in[7];
    const float* kb     = (const float*)d_in[8];
    const float* n1     = (const float*)d_in[9];
    const float* n2     = (const float*)d_in[10];
    float* out = (float*)d_out;

    float *xn, *val, *keys;
    __nv_bfloat16 *Ah, *Al, *vwh, *vwl, *kwh, *kwl;
    cudaGetSymbolAddress((void**)&xn,   g_xn);
    cudaGetSymbolAddress((void**)&val,  g_value);
    cudaGetSymbolAddress((void**)&keys, g_keys);
    cudaGetSymbolAddress((void**)&Ah,   g_Ah);
    cudaGetSymbolAddress((void**)&Al,   g_Al);
    cudaGetSymbolAddress((void**)&vwh,  g_vwh);
    cudaGetSymbolAddress((void**)&vwl,  g_vwl);
    cudaGetSymbolAddress((void**)&kwh,  g_kwh);
    cudaGetSymbolAddress((void**)&kwl,  g_kwl);

    static bool attr_set = false;
    if (!attr_set) {
        cudaFuncSetAttribute(gemm_mma, cudaFuncAttributeMaxDynamicSharedMemorySize, GEMM_SMEM);
        attr_set = true;
    }

    gather_split_k<<<BT, 256>>>(hash, tab, Ah, Al);
    wsplit_k<<<(EMB * HID / 4 + 255) / 256, 256>>>(vw, vwh, vwl, EMB * HID / 4);
    wsplit_k<<<(CCH * HID / 4 + 255) / 256, 256>>>(kw, kwh, kwl, CCH * HID / 4);
    rms_sc_k<<<BT * GDIM, 256>>>(hidden, scw, xn);

    dim3 gv(EMB / 128, BT / 128);
    gemm_mma<<<gv, 256, GEMM_SMEM>>>(Ah, Al, vwh, vwl, vb, val, EMB);

    dim3 gk(CCH / 128, BT / 128);
    gemm_mma<<<gk, 256, GEMM_SMEM>>>(Ah, Al, kwh, kwl, kb, keys, CCH);

    final_k<<<BT * GDIM, 256>>>(xn, convw, keys, val, n1, n2, out);
}

// round 9
// speedup vs baseline: 2.5270x; 1.1184x over previous
#include <cuda_runtime.h>
#include <cuda_bf16.h>
#include <cstdint>

// ---------------------------------------------------------------------------
// Problem constants
// ---------------------------------------------------------------------------
#define BATCH   4
#define TLEN    2048
#define BT      8192
#define GDIM    4
#define HID     1024
#define NHEADS  16
#define DHEAD   64
#define EMB     1024
#define CCH     4096
#define KS      4
#define DIL     3

// ---------------------------------------------------------------------------
// Compile-time per-head vocab offsets (prime search; mirrors reference)
// ---------------------------------------------------------------------------
constexpr bool c_isprime(long long n) {
    if (n < 2) return false;
    if (n % 2 == 0) return n == 2;
    for (long long i = 3; i * i <= n; i += 2)
        if (n % i == 0) return false;
    return true;
}
struct OffT { long long off[16]; };
constexpr OffT make_off() {
    long long sizes[16] = {};
    int idx = 0;
    for (int ng = 0; ng < 2; ng++) {
        long long start = 129280 - 1;
        for (int h = 0; h < 8; h++) {
            long long c = start + 1;
            for (;;) {
                bool ok = c_isprime(c);
                if (ok) for (int j = 0; j < idx; j++) if (sizes[j] == c) { ok = false; break; }
                if (ok) break;
                ++c;
            }
            sizes[idx++] = c;
            start = c;
        }
    }
    OffT o{};
    long long acc = 0;
    for (int i = 0; i < 16; i++) { o.off[i] = acc; acc += sizes[i]; }
    return o;
}
constexpr OffT HOFF = make_off();
__constant__ long long d_off[16] = {
    HOFF.off[0], HOFF.off[1], HOFF.off[2], HOFF.off[3],
    HOFF.off[4], HOFF.off[5], HOFF.off[6], HOFF.off[7],
    HOFF.off[8], HOFF.off[9], HOFF.off[10], HOFF.off[11],
    HOFF.off[12], HOFF.off[13], HOFF.off[14], HOFF.off[15]
};

// ---------------------------------------------------------------------------
// Scratch (device globals)
// ---------------------------------------------------------------------------
__device__ float g_A    [(size_t)BT * EMB];      //  32 MB (tf32-rounded embs)
__device__ float g_value[(size_t)BT * EMB];      //  32 MB
__device__ float g_keys [(size_t)BT * CCH];      // 128 MB
__device__ float g_vwt  [(size_t)EMB * HID];     //   4 MB (tf32-rounded value_w)
__device__ float g_kwt  [(size_t)CCH * HID];     //  16 MB (tf32-rounded key_w)

// ---------------------------------------------------------------------------
// PTX helpers (sm_80-era: cp.async, ldmatrix, mma.sync — valid on compute_103)
// ---------------------------------------------------------------------------
__device__ __forceinline__ uint32_t smem_u32(const void* p) {
    uint32_t a;
    asm("{ .reg .u64 t; cvta.to.shared.u64 t, %1; cvt.u32.u64 %0, t; }" : "=r"(a) : "l"(p));
    return a;
}

__device__ __forceinline__ float to_tf32(float x) {
    uint32_t r;
    asm("cvt.rna.tf32.f32 %0, %1;" : "=r"(r) : "f"(x));
    return __uint_as_float(r);
}

#define CP16(sm, gm) asm volatile("cp.async.ca.shared.global [%0], [%1], 16;" :: "r"(sm), "l"(gm))
#define CPCOMMIT()   asm volatile("cp.async.commit_group;" ::: "memory")
#define CPWAIT(n)    asm volatile("cp.async.wait_group %0;" :: "n"(n) : "memory")

#define LDSM4(r0, r1, r2, r3, a)                                           \
    asm volatile("ldmatrix.sync.aligned.m8n8.x4.shared.b16 {%0,%1,%2,%3}, [%4];" \
        : "=r"(r0), "=r"(r1), "=r"(r2), "=r"(r3) : "r"(a))

#define LDSM2(r0, r1, a)                                                   \
    asm volatile("ldmatrix.sync.aligned.m8n8.x2.shared.b16 {%0,%1}, [%2];" \
        : "=r"(r0), "=r"(r1) : "r"(a))

#define MMA1688(d, a, b0, b1)                                              \
    asm volatile("mma.sync.aligned.m16n8k8.row.col.f32.tf32.tf32.f32 "     \
        "{%0,%1,%2,%3}, {%4,%5,%6,%7}, {%8,%9}, {%0,%1,%2,%3};"            \
        : "+f"((d)[0]), "+f"((d)[1]), "+f"((d)[2]), "+f"((d)[3])           \
        : "r"((a)[0]), "r"((a)[1]), "r"((a)[2]), "r"((a)[3]),              \
          "r"(b0), "r"(b1))

// Swizzle for 128B rows (8 x 16B chunks), full 8-way XOR:
//   byte offset = row*128 + ((ch ^ (row&7)) * 16)
__device__ __forceinline__ uint32_t sofs32(int row, int ch) {
    return (uint32_t)(row * 128 + ((ch ^ (row & 7)) << 4));
}

#define TF_ABYTES 16384               // 128 rows x 32 fp32
#define TF_BUFSZ  (2 * TF_ABYTES)     // A tile + B tile
#define TF_SMEM   (2 * TF_BUFSZ)      // double buffered = 64 KB

// ---------------------------------------------------------------------------
// Single-pass TF32 NT GEMM via mma.sync.m16n8k8:
//   C[m,n] = sum_k A[m,k]*B[n,k] + bias[n]   (A, B tf32-rounded fp32, K=1024)
//   Tile 128x128, BK=32, 8 warps (2x4), warp tile 64x32, cp.async dbl buffer.
// ---------------------------------------------------------------------------
__global__ __launch_bounds__(256, 2)
void gemm_tf32(const float* __restrict__ A, const float* __restrict__ B,
               const float* __restrict__ bias, float* __restrict__ C, int ldc) {
    extern __shared__ __align__(128) char smem[];
    const uint32_t sb = smem_u32(smem);

    const int tid = threadIdx.x;
    const int lane = tid & 31, wid = tid >> 5;
    const int wm = wid >> 2, wn = wid & 3;            // warp grid 2x4
    const int bm = blockIdx.y * 128, bn = blockIdx.x * 128;

    const int lrow = tid >> 1;                        // 0..127
    const int lch0 = (tid & 1) * 4;                   // chunk half 0..3 / 4..7

    float acc[4][4][4];
    #pragma unroll
    for (int i = 0; i < 4; i++)
        #pragma unroll
        for (int j = 0; j < 4; j++)
            #pragma unroll
            for (int q = 0; q < 4; q++) acc[i][j][q] = 0.f;

    auto issue = [&](int kc, int buf) {
        uint32_t base = sb + buf * TF_BUFSZ;
        const float* ga = A + (size_t)(bm + lrow) * 1024 + kc * 32;
        const float* gb = B + (size_t)(bn + lrow) * 1024 + kc * 32;
        #pragma unroll
        for (int i = 0; i < 4; i++) {
            int ch = lch0 + i;
            uint32_t so = sofs32(lrow, ch);
            CP16(base + so, ga + ch * 4);
            CP16(base + TF_ABYTES + so, gb + ch * 4);
        }
        CPCOMMIT();
    };

    issue(0, 0);

    for (int kc = 0; kc < 32; kc++) {
        int buf = kc & 1;
        if (kc + 1 < 32) {
            issue(kc + 1, buf ^ 1);
            CPWAIT(1);
        } else {
            CPWAIT(0);
        }
        __syncthreads();

        uint32_t baseA = sb + buf * TF_BUFSZ;
        uint32_t baseB = baseA + TF_ABYTES;

        #pragma unroll
        for (int ks = 0; ks < 4; ks++) {
            // A fragments: ldmatrix.x4 -> {a0,a1,a2,a3} of m16k8 tf32
            const int arow_l = wm * 64 + (lane & 7) + ((lane >> 3) & 1) * 8;
            const int ach = ks * 2 + (lane >> 4);
            uint32_t af[4][4];
            #pragma unroll
            for (int mi = 0; mi < 4; mi++) {
                int rr = arow_l + mi * 16;
                LDSM4(af[mi][0], af[mi][1], af[mi][2], af[mi][3],
                      baseA + sofs32(rr, ach));
            }
            // B fragments: ldmatrix.x2 -> {b0,b1} of n8k8 tf32
            const int brow_l = wn * 32 + (lane & 7);
            const int bch = ks * 2 + ((lane >> 3) & 1);
            uint32_t bf[4][2];
            #pragma unroll
            for (int nj = 0; nj < 4; nj++) {
                int rr = brow_l + nj * 8;
                LDSM2(bf[nj][0], bf[nj][1], baseB + sofs32(rr, bch));
            }
            #pragma unroll
            for (int mi = 0; mi < 4; mi++)
                #pragma unroll
                for (int nj = 0; nj < 4; nj++)
                    MMA1688(acc[mi][nj], af[mi], bf[nj][0], bf[nj][1]);
        }
        __syncthreads();
    }

    // epilogue: m16n8 C fragment: c0=(r,c), c1=(r,c+1), c2=(r+8,c), c3=(r+8,c+1)
    #pragma unroll
    for (int mi = 0; mi < 4; mi++) {
        int r0 = bm + wm * 64 + mi * 16 + (lane >> 2);
        #pragma unroll
        for (int nj = 0; nj < 4; nj++) {
            int c = bn + wn * 32 + nj * 8 + (lane & 3) * 2;
            float2 bv = *(const float2*)&bias[c];
            float2 o0, o1;
            o0.x = acc[mi][nj][0] + bv.x;
            o0.y = acc[mi][nj][1] + bv.y;
            o1.x = acc[mi][nj][2] + bv.x;
            o1.y = acc[mi][nj][3] + bv.y;
            *(float2*)&C[(size_t)r0 * ldc + c]       = o0;
            *(float2*)&C[(size_t)(r0 + 8) * ldc + c] = o1;
        }
    }
}

// ---------------------------------------------------------------------------
// Embedding gather, tf32-rounded (grid=BT, block=256)
// ---------------------------------------------------------------------------
__global__ void gather_k(const int* __restrict__ hash,
                         const float* __restrict__ tab,
                         float* __restrict__ A) {
    int bt = blockIdx.x;
    int tid = threadIdx.x;
    int h = tid >> 4;
    int q = tid & 15;
    long long row = (long long)hash[(size_t)bt * NHEADS + h] + d_off[h];
    float4 v = *(const float4*)&tab[row * DHEAD + q * 4];
    float4 o;
    o.x = to_tf32(v.x); o.y = to_tf32(v.y);
    o.z = to_tf32(v.z); o.w = to_tf32(v.w);
    *(float4*)&A[(size_t)bt * EMB + h * DHEAD + q * 4] = o;
}

// ---------------------------------------------------------------------------
// Weight tf32 rounding (n4 float4 elements)
// ---------------------------------------------------------------------------
__global__ void wround_k(const float* __restrict__ w, float* __restrict__ o4, int n4) {
    int i = blockIdx.x * blockDim.x + threadIdx.x;
    if (i >= n4) return;
    float4 v = ((const float4*)w)[i];
    float4 o;
    o.x = to_tf32(v.x); o.y = to_tf32(v.y);
    o.z = to_tf32(v.z); o.w = to_tf32(v.w);
    ((float4*)o4)[i] = o;
}

// ---------------------------------------------------------------------------
// Reductions
// ---------------------------------------------------------------------------
__device__ __forceinline__ void block_reduce4(float v[4]) {
    #pragma unroll
    for (int o = 16; o; o >>= 1)
        #pragma unroll
        for (int q = 0; q < 4; q++) v[q] += __shfl_xor_sync(0xffffffffu, v[q], o);
    __shared__ float s[8][4];
    int w = threadIdx.x >> 5, l = threadIdx.x & 31;
    if (l == 0) { s[w][0] = v[0]; s[w][1] = v[1]; s[w][2] = v[2]; s[w][3] = v[3]; }
    __syncthreads();
    if (w == 0) {
        #pragma unroll
        for (int q = 0; q < 4; q++) v[q] = (l < 8) ? s[l][q] : 0.f;
        #pragma unroll
        for (int o = 4; o; o >>= 1)
            #pragma unroll
            for (int q = 0; q < 4; q++) v[q] += __shfl_xor_sync(0xffffffffu, v[q], o);
        if (l == 0) { s[0][0] = v[0]; s[0][1] = v[1]; s[0][2] = v[2]; s[0][3] = v[3]; }
    }
    __syncthreads();
    v[0] = s[0][0]; v[1] = s[0][1]; v[2] = s[0][2]; v[3] = s[0][3];
}

__device__ __forceinline__ float3 block_reduce3(float a, float b, float c) {
    #pragma unroll
    for (int o = 16; o; o >>= 1) {
        a += __shfl_xor_sync(0xffffffffu, a, o);
        b += __shfl_xor_sync(0xffffffffu, b, o);
        c += __shfl_xor_sync(0xffffffffu, c, o);
    }
    __shared__ float sa[8], sb[8], sc[8];
    int w = threadIdx.x >> 5, l = threadIdx.x & 31;
    if (l == 0) { sa[w] = a; sb[w] = b; sc[w] = c; }
    __syncthreads();
    if (w == 0) {
        a = (l < 8) ? sa[l] : 0.f;
        b = (l < 8) ? sb[l] : 0.f;
        c = (l < 8) ? sc[l] : 0.f;
        #pragma unroll
        for (int o = 4; o; o >>= 1) {
            a += __shfl_xor_sync(0xffffffffu, a, o);
            b += __shfl_xor_sync(0xffffffffu, b, o);
            c += __shfl_xor_sync(0xffffffffu, c, o);
        }
        if (l == 0) { sa[0] = a; sb[0] = b; sc[0] = c; }
    }
    __syncthreads();
    return make_float3(sa[0], sb[0], sc[0]);
}

// ---------------------------------------------------------------------------
// Final fused kernel: rms(hidden) on the fly -> conv -> silu -> q-rms ;
// k-rms ; gate ; out.  grid = BT*GDIM, block = 256.
// ---------------------------------------------------------------------------
__global__ void final_k(const float* __restrict__ hidden,
                        const float* __restrict__ scw,
                        const float* __restrict__ convw,
                        const float* __restrict__ keys,
                        const float* __restrict__ value,
                        const float* __restrict__ n1w,
                        const float* __restrict__ n2w,
                        float* __restrict__ out) {
    int r = blockIdx.x;
    int g = r & 3;
    int bt = r >> 2;
    int t = bt & (TLEN - 1);
    int tid = threadIdx.x;
    int d = tid * 4;

    // load the KS hidden rows (dilated taps) + per-row sum of squares
    float4 hx[KS];
    float ss[KS];
    #pragma unroll
    for (int k = 0; k < KS; k++) {
        int tp = t - (KS - 1 - k) * DIL;
        if (tp >= 0) {
            size_t row = ((size_t)(bt - (KS - 1 - k) * DIL) * GDIM + g);
            hx[k] = *(const float4*)&hidden[row * HID + d];
        } else {
            hx[k] = make_float4(0.f, 0.f, 0.f, 0.f);
        }
        ss[k] = hx[k].x*hx[k].x + hx[k].y*hx[k].y + hx[k].z*hx[k].z + hx[k].w*hx[k].w;
    }
    block_reduce4(ss);
    float rs[KS];
    #pragma unroll
    for (int k = 0; k < KS; k++)
        rs[k] = rsqrtf(ss[k] * (1.f / HID) + 1e-5f);

    // conv taps: w[ch][k], ch = g*1024 + d + j
    const float4* wb = (const float4*)(convw + (size_t)(g * HID + d) * KS);
    float4 w0 = wb[0], w1 = wb[1], w2 = wb[2], w3 = wb[3];
    float4 sw = *(const float4*)&scw[(size_t)g * HID + d];

    float y0 = 0.f, y1 = 0.f, y2 = 0.f, y3 = 0.f;
    #pragma unroll
    for (int k = 0; k < KS; k++) {
        float rsk = rs[k];
        y0 = fmaf(hx[k].x * rsk, ((const float*)&w0)[k], y0);
        y1 = fmaf(hx[k].y * rsk, ((const float*)&w1)[k], y1);
        y2 = fmaf(hx[k].z * rsk, ((const float*)&w2)[k], y2);
        y3 = fmaf(hx[k].w * rsk, ((const float*)&w3)[k], y3);
    }
    y0 *= sw.x; y1 *= sw.y; y2 *= sw.z; y3 *= sw.w;

    // silu
    float s0 = y0 / (1.f + __expf(-y0));
    float s1 = y1 / (1.f + __expf(-y1));
    float s2 = y2 / (1.f + __expf(-y2));
    float s3 = y3 / (1.f + __expf(-y3));

    float4 kv = *(const float4*)&keys[(size_t)bt * CCH + g * HID + d];
    float4 n1 = *(const float4*)&n1w[(size_t)g * HID + d];
    float4 n2 = *(const float4*)&n2w[(size_t)g * HID + d];

    float ssq = s0*s0 + s1*s1 + s2*s2 + s3*s3;
    float ksq = kv.x*kv.x + kv.y*kv.y + kv.z*kv.z + kv.w*kv.w;
    float dot = s0*kv.x*n1.x*n2.x + s1*kv.y*n1.y*n2.y
              + s2*kv.z*n1.z*n2.z + s3*kv.w*n1.w*n2.w;

    float3 red = block_reduce3(ssq, ksq, dot);

    float rq = rsqrtf(red.x * (1.f / HID) + 1e-6f);
    float rk = rsqrtf(red.y * (1.f / HID) + 1e-6f);
    float z  = red.z * rq * rk * (1.f / 32.f);
    float gate = 1.f / (1.f + __expf(-z));

    float4 vv = *(const float4*)&value[(size_t)bt * EMB + d];
    float4 o;
    o.x = gate * vv.x; o.y = gate * vv.y;
    o.z = gate * vv.z; o.w = gate * vv.w;
    *(float4*)&out[(size_t)r * HID + d] = o;
}

// ---------------------------------------------------------------------------
// Launch
// ---------------------------------------------------------------------------
extern "C" void kernel_launch(void* const* d_in, const int* in_sizes, int n_in,
                              void* d_out, int out_size) {
    const float* hidden = (const float*)d_in[0];
    const int*   hash   = (const int*)d_in[1];
    const float* tab    = (const float*)d_in[2];
    const float* convw  = (const float*)d_in[3];
    const float* scw    = (const float*)d_in[4];
    const float* vw     = (const float*)d_in[5];
    const float* vb     = (const float*)d_in[6];
    const float* kw     = (const float*)d_in[7];
    const float* kb     = (const float*)d_in[8];
    const float* n1     = (const float*)d_in[9];
    const float* n2     = (const float*)d_in[10];
    float* out = (float*)d_out;

    float *A, *val, *keys, *vwt, *kwt;
    cudaGetSymbolAddress((void**)&A,    g_A);
    cudaGetSymbolAddress((void**)&val,  g_value);
    cudaGetSymbolAddress((void**)&keys, g_keys);
    cudaGetSymbolAddress((void**)&vwt,  g_vwt);
    cudaGetSymbolAddress((void**)&kwt,  g_kwt);

    cudaFuncSetAttribute(gemm_tf32, cudaFuncAttributeMaxDynamicSharedMemorySize, TF_SMEM);

    gather_k<<<BT, 256>>>(hash, tab, A);
    wround_k<<<(EMB * HID / 4 + 255) / 256, 256>>>(vw, vwt, EMB * HID / 4);
    wround_k<<<(CCH * HID / 4 + 255) / 256, 256>>>(kw, kwt, CCH * HID / 4);

    dim3 gv(EMB / 128, BT / 128);
    gemm_tf32<<<gv, 256, TF_SMEM>>>(A, vwt, vb, val, EMB);

    dim3 gk(CCH / 128, BT / 128);
    gemm_tf32<<<gk, 256, TF_SMEM>>>(A, kwt, kb, keys, CCH);

    final_k<<<BT * GDIM, 256>>>(hidden, scw, convw, keys, val, n1, n2, out);
}

// round 10
// speedup vs baseline: 2.9016x; 1.1482x over previous
#include <cuda_runtime.h>
#include <cuda_bf16.h>
#include <cstdint>

// ---------------------------------------------------------------------------
// Problem constants
// ---------------------------------------------------------------------------
#define BATCH   4
#define TLEN    2048
#define BT      8192
#define GDIM    4
#define HID     1024
#define NHEADS  16
#define DHEAD   64
#define EMB     1024
#define CCH     4096
#define KS      4
#define DIL     3

// ---------------------------------------------------------------------------
// Compile-time per-head vocab offsets (prime search; mirrors reference)
// ---------------------------------------------------------------------------
constexpr bool c_isprime(long long n) {
    if (n < 2) return false;
    if (n % 2 == 0) return n == 2;
    for (long long i = 3; i * i <= n; i += 2)
        if (n % i == 0) return false;
    return true;
}
struct OffT { long long off[16]; };
constexpr OffT make_off() {
    long long sizes[16] = {};
    int idx = 0;
    for (int ng = 0; ng < 2; ng++) {
        long long start = 129280 - 1;
        for (int h = 0; h < 8; h++) {
            long long c = start + 1;
            for (;;) {
                bool ok = c_isprime(c);
                if (ok) for (int j = 0; j < idx; j++) if (sizes[j] == c) { ok = false; break; }
                if (ok) break;
                ++c;
            }
            sizes[idx++] = c;
            start = c;
        }
    }
    OffT o{};
    long long acc = 0;
    for (int i = 0; i < 16; i++) { o.off[i] = acc; acc += sizes[i]; }
    return o;
}
constexpr OffT HOFF = make_off();
__constant__ long long d_off[16] = {
    HOFF.off[0], HOFF.off[1], HOFF.off[2], HOFF.off[3],
    HOFF.off[4], HOFF.off[5], HOFF.off[6], HOFF.off[7],
    HOFF.off[8], HOFF.off[9], HOFF.off[10], HOFF.off[11],
    HOFF.off[12], HOFF.off[13], HOFF.off[14], HOFF.off[15]
};

// ---------------------------------------------------------------------------
// Scratch (device globals)
// ---------------------------------------------------------------------------
__device__ float g_A    [(size_t)BT * EMB];      //  32 MB (tf32-rounded embs)
__device__ float g_value[(size_t)BT * EMB];      //  32 MB
__device__ float g_keys [(size_t)BT * CCH];      // 128 MB
__device__ float g_vwt  [(size_t)EMB * HID];     //   4 MB (tf32-rounded value_w)
__device__ float g_kwt  [(size_t)CCH * HID];     //  16 MB (tf32-rounded key_w)

// ---------------------------------------------------------------------------
// PTX helpers
// ---------------------------------------------------------------------------
__device__ __forceinline__ uint32_t smem_u32(const void* p) {
    uint32_t a;
    asm("{ .reg .u64 t; cvta.to.shared.u64 t, %1; cvt.u32.u64 %0, t; }" : "=r"(a) : "l"(p));
    return a;
}

__device__ __forceinline__ float to_tf32(float x) {
    uint32_t r;
    asm("cvt.rna.tf32.f32 %0, %1;" : "=r"(r) : "f"(x));
    return __uint_as_float(r);
}

#define CP16(sm, gm) asm volatile("cp.async.ca.shared.global [%0], [%1], 16;" :: "r"(sm), "l"(gm))
#define CPCOMMIT()   asm volatile("cp.async.commit_group;" ::: "memory")
#define CPWAIT(n)    asm volatile("cp.async.wait_group %0;" :: "n"(n) : "memory")

#define LDSM4(r0, r1, r2, r3, a)                                           \
    asm volatile("ldmatrix.sync.aligned.m8n8.x4.shared.b16 {%0,%1,%2,%3}, [%4];" \
        : "=r"(r0), "=r"(r1), "=r"(r2), "=r"(r3) : "r"(a))

#define MMA1688(d, a, b0, b1)                                              \
    asm volatile("mma.sync.aligned.m16n8k8.row.col.f32.tf32.tf32.f32 "     \
        "{%0,%1,%2,%3}, {%4,%5,%6,%7}, {%8,%9}, {%0,%1,%2,%3};"            \
        : "+f"((d)[0]), "+f"((d)[1]), "+f"((d)[2]), "+f"((d)[3])           \
        : "r"((a)[0]), "r"((a)[1]), "r"((a)[2]), "r"((a)[3]),              \
          "r"(b0), "r"(b1))

// Swizzle for 128B rows (8 x 16B chunks): byte = row*128 + ((ch ^ (row&7))*16)
__device__ __forceinline__ uint32_t sofs32(int row, int ch) {
    return (uint32_t)(row * 128 + ((ch ^ (row & 7)) << 4));
}

#define TFB_A     16384               // A: 128 rows x 128B
#define TFB_B     32768               // B: 256 rows x 128B
#define TFB_BUF   (TFB_A + TFB_B)     // 48 KB per stage
#define TFB_SMEM  (2 * TFB_BUF)       // 96 KB double buffered

// ---------------------------------------------------------------------------
// Single-pass TF32 NT GEMM, fat tiles:
//   C[m,n] = sum_k A[m,k]*B[n,k] + bias[n]   (K = 1024)
//   Block tile 128x256, 8 warps (2x4), warp tile 64x64, BK=32,
//   cp.async double buffer, 1 CTA/SM.
// ---------------------------------------------------------------------------
__global__ __launch_bounds__(256, 1)
void gemm_tf32(const float* __restrict__ A, const float* __restrict__ B,
               const float* __restrict__ bias, float* __restrict__ C, int ldc) {
    extern __shared__ __align__(128) char smem[];
    const uint32_t sb = smem_u32(smem);

    const int tid = threadIdx.x;
    const int lane = tid & 31, wid = tid >> 5;
    const int wm = wid >> 2, wn = wid & 3;            // warp grid 2x4
    const int bm = blockIdx.y * 128, bn = blockIdx.x * 256;

    const int lrow = tid >> 1;                        // 0..127
    const int lch0 = (tid & 1) * 4;                   // chunk half

    float acc[4][8][4];
    #pragma unroll
    for (int i = 0; i < 4; i++)
        #pragma unroll
        for (int j = 0; j < 8; j++)
            #pragma unroll
            for (int q = 0; q < 4; q++) acc[i][j][q] = 0.f;

    auto issue = [&](int kc, int buf) {
        uint32_t base = sb + buf * TFB_BUF;
        const float* ga = A + (size_t)(bm + lrow) * 1024 + kc * 32;
        #pragma unroll
        for (int i = 0; i < 4; i++) {
            int ch = lch0 + i;
            CP16(base + sofs32(lrow, ch), ga + ch * 4);
        }
        #pragma unroll
        for (int r2 = 0; r2 < 2; r2++) {
            int brow = lrow + r2 * 128;
            const float* gb = B + (size_t)(bn + brow) * 1024 + kc * 32;
            #pragma unroll
            for (int i = 0; i < 4; i++) {
                int ch = lch0 + i;
                CP16(base + TFB_A + sofs32(brow, ch), gb + ch * 4);
            }
        }
        CPCOMMIT();
    };

    issue(0, 0);

    for (int kc = 0; kc < 32; kc++) {
        int buf = kc & 1;
        if (kc + 1 < 32) {
            issue(kc + 1, buf ^ 1);
            CPWAIT(1);
        } else {
            CPWAIT(0);
        }
        __syncthreads();

        uint32_t baseA = sb + buf * TFB_BUF;
        uint32_t baseB = baseA + TFB_A;

        #pragma unroll
        for (int ks = 0; ks < 4; ks++) {
            // A fragments (m16k8 x4 tiles): x4 = {rows, rows+8} x {k0-3, k4-7}
            const int arow_l = wm * 64 + (lane & 7) + ((lane >> 3) & 1) * 8;
            const int ach = ks * 2 + (lane >> 4);
            uint32_t af[4][4];
            #pragma unroll
            for (int mi = 0; mi < 4; mi++)
                LDSM4(af[mi][0], af[mi][1], af[mi][2], af[mi][3],
                      baseA + sofs32(arow_l + mi * 16, ach));

            // B fragments: one LDSM4 covers two n8 tiles:
            //   m0/m1 = tile 2p {k0,k1-half}, m2/m3 = tile 2p+1
            const int brow_l = wn * 64 + (lane & 7) + ((lane >> 4) & 1) * 8;
            const int bch = ks * 2 + ((lane >> 3) & 1);
            uint32_t bf[8][2];
            #pragma unroll
            for (int p = 0; p < 4; p++)
                LDSM4(bf[2 * p][0], bf[2 * p][1], bf[2 * p + 1][0], bf[2 * p + 1][1],
                      baseB + sofs32(brow_l + p * 16, bch));

            #pragma unroll
            for (int mi = 0; mi < 4; mi++)
                #pragma unroll
                for (int nj = 0; nj < 8; nj++)
                    MMA1688(acc[mi][nj], af[mi], bf[nj][0], bf[nj][1]);
        }
        __syncthreads();
    }

    // epilogue: m16n8 fragment: c0=(r,c) c1=(r,c+1) c2=(r+8,c) c3=(r+8,c+1)
    #pragma unroll
    for (int mi = 0; mi < 4; mi++) {
        int r0 = bm + wm * 64 + mi * 16 + (lane >> 2);
        #pragma unroll
        for (int nj = 0; nj < 8; nj++) {
            int c = bn + wn * 64 + nj * 8 + (lane & 3) * 2;
            float2 bv = *(const float2*)&bias[c];
            float2 o0, o1;
            o0.x = acc[mi][nj][0] + bv.x;
            o0.y = acc[mi][nj][1] + bv.y;
            o1.x = acc[mi][nj][2] + bv.x;
            o1.y = acc[mi][nj][3] + bv.y;
            *(float2*)&C[(size_t)r0 * ldc + c]       = o0;
            *(float2*)&C[(size_t)(r0 + 8) * ldc + c] = o1;
        }
    }
}

// ---------------------------------------------------------------------------
// Embedding gather, tf32-rounded (grid=BT, block=256)
// ---------------------------------------------------------------------------
__global__ void gather_k(const int* __restrict__ hash,
                         const float* __restrict__ tab,
                         float* __restrict__ A) {
    int bt = blockIdx.x;
    int tid = threadIdx.x;
    int h = tid >> 4;
    int q = tid & 15;
    long long row = (long long)hash[(size_t)bt * NHEADS + h] + d_off[h];
    float4 v = *(const float4*)&tab[row * DHEAD + q * 4];
    float4 o;
    o.x = to_tf32(v.x); o.y = to_tf32(v.y);
    o.z = to_tf32(v.z); o.w = to_tf32(v.w);
    *(float4*)&A[(size_t)bt * EMB + h * DHEAD + q * 4] = o;
}

// ---------------------------------------------------------------------------
// Weight tf32 rounding
// ---------------------------------------------------------------------------
__global__ void wround_k(const float* __restrict__ w, float* __restrict__ o4, int n4) {
    int i = blockIdx.x * blockDim.x + threadIdx.x;
    if (i >= n4) return;
    float4 v = ((const float4*)w)[i];
    float4 o;
    o.x = to_tf32(v.x); o.y = to_tf32(v.y);
    o.z = to_tf32(v.z); o.w = to_tf32(v.w);
    ((float4*)o4)[i] = o;
}

// ---------------------------------------------------------------------------
// Reductions
// ---------------------------------------------------------------------------
__device__ __forceinline__ void block_reduce4(float v[4]) {
    #pragma unroll
    for (int o = 16; o; o >>= 1)
        #pragma unroll
        for (int q = 0; q < 4; q++) v[q] += __shfl_xor_sync(0xffffffffu, v[q], o);
    __shared__ float s[8][4];
    int w = threadIdx.x >> 5, l = threadIdx.x & 31;
    if (l == 0) { s[w][0] = v[0]; s[w][1] = v[1]; s[w][2] = v[2]; s[w][3] = v[3]; }
    __syncthreads();
    if (w == 0) {
        #pragma unroll
        for (int q = 0; q < 4; q++) v[q] = (l < 8) ? s[l][q] : 0.f;
        #pragma unroll
        for (int o = 4; o; o >>= 1)
            #pragma unroll
            for (int q = 0; q < 4; q++) v[q] += __shfl_xor_sync(0xffffffffu, v[q], o);
        if (l == 0) { s[0][0] = v[0]; s[0][1] = v[1]; s[0][2] = v[2]; s[0][3] = v[3]; }
    }
    __syncthreads();
    v[0] = s[0][0]; v[1] = s[0][1]; v[2] = s[0][2]; v[3] = s[0][3];
}

__device__ __forceinline__ float3 block_reduce3(float a, float b, float c) {
    #pragma unroll
    for (int o = 16; o; o >>= 1) {
        a += __shfl_xor_sync(0xffffffffu, a, o);
        b += __shfl_xor_sync(0xffffffffu, b, o);
        c += __shfl_xor_sync(0xffffffffu, c, o);
    }
    __shared__ float sa[8], sb[8], sc[8];
    int w = threadIdx.x >> 5, l = threadIdx.x & 31;
    if (l == 0) { sa[w] = a; sb[w] = b; sc[w] = c; }
    __syncthreads();
    if (w == 0) {
        a = (l < 8) ? sa[l] : 0.f;
        b = (l < 8) ? sb[l] : 0.f;
        c = (l < 8) ? sc[l] : 0.f;
        #pragma unroll
        for (int o = 4; o; o >>= 1) {
            a += __shfl_xor_sync(0xffffffffu, a, o);
            b += __shfl_xor_sync(0xffffffffu, b, o);
            c += __shfl_xor_sync(0xffffffffu, c, o);
        }
        if (l == 0) { sa[0] = a; sb[0] = b; sc[0] = c; }
    }
    __syncthreads();
    return make_float3(sa[0], sb[0], sc[0]);
}

// ---------------------------------------------------------------------------
// Final fused kernel: rms(hidden) on the fly -> conv -> silu -> q-rms ;
// k-rms ; gate ; out.  grid = BT*GDIM, block = 256.
// ---------------------------------------------------------------------------
__global__ void final_k(const float* __restrict__ hidden,
                        const float* __restrict__ scw,
                        const float* __restrict__ convw,
                        const float* __restrict__ keys,
                        const float* __restrict__ value,
                        const float* __restrict__ n1w,
                        const float* __restrict__ n2w,
                        float* __restrict__ out) {
    int r = blockIdx.x;
    int g = r & 3;
    int bt = r >> 2;
    int t = bt & (TLEN - 1);
    int tid = threadIdx.x;
    int d = tid * 4;

    float4 hx[KS];
    float ss[KS];
    #pragma unroll
    for (int k = 0; k < KS; k++) {
        int tp = t - (KS - 1 - k) * DIL;
        if (tp >= 0) {
            size_t row = ((size_t)(bt - (KS - 1 - k) * DIL) * GDIM + g);
            hx[k] = *(const float4*)&hidden[row * HID + d];
        } else {
            hx[k] = make_float4(0.f, 0.f, 0.f, 0.f);
        }
        ss[k] = hx[k].x*hx[k].x + hx[k].y*hx[k].y + hx[k].z*hx[k].z + hx[k].w*hx[k].w;
    }
    block_reduce4(ss);
    float rs[KS];
    #pragma unroll
    for (int k = 0; k < KS; k++)
        rs[k] = rsqrtf(ss[k] * (1.f / HID) + 1e-5f);

    const float4* wb = (const float4*)(convw + (size_t)(g * HID + d) * KS);
    float4 w0 = wb[0], w1 = wb[1], w2 = wb[2], w3 = wb[3];
    float4 sw = *(const float4*)&scw[(size_t)g * HID + d];

    float y0 = 0.f, y1 = 0.f, y2 = 0.f, y3 = 0.f;
    #pragma unroll
    for (int k = 0; k < KS; k++) {
        float rsk = rs[k];
        y0 = fmaf(hx[k].x * rsk, ((const float*)&w0)[k], y0);
        y1 = fmaf(hx[k].y * rsk, ((const float*)&w1)[k], y1);
        y2 = fmaf(hx[k].z * rsk, ((const float*)&w2)[k], y2);
        y3 = fmaf(hx[k].w * rsk, ((const float*)&w3)[k], y3);
    }
    y0 *= sw.x; y1 *= sw.y; y2 *= sw.z; y3 *= sw.w;

    float s0 = y0 / (1.f + __expf(-y0));
    float s1 = y1 / (1.f + __expf(-y1));
    float s2 = y2 / (1.f + __expf(-y2));
    float s3 = y3 / (1.f + __expf(-y3));

    float4 kv = *(const float4*)&keys[(size_t)bt * CCH + g * HID + d];
    float4 n1 = *(const float4*)&n1w[(size_t)g * HID + d];
    float4 n2 = *(const float4*)&n2w[(size_t)g * HID + d];

    float ssq = s0*s0 + s1*s1 + s2*s2 + s3*s3;
    float ksq = kv.x*kv.x + kv.y*kv.y + kv.z*kv.z + kv.w*kv.w;
    float dot = s0*kv.x*n1.x*n2.x + s1*kv.y*n1.y*n2.y
              + s2*kv.z*n1.z*n2.z + s3*kv.w*n1.w*n2.w;

    float3 red = block_reduce3(ssq, ksq, dot);

    float rq = rsqrtf(red.x * (1.f / HID) + 1e-6f);
    float rk = rsqrtf(red.y * (1.f / HID) + 1e-6f);
    float z  = red.z * rq * rk * (1.f / 32.f);
    float gate = 1.f / (1.f + __expf(-z));

    float4 vv = *(const float4*)&value[(size_t)bt * EMB + d];
    float4 o;
    o.x = gate * vv.x; o.y = gate * vv.y;
    o.z = gate * vv.z; o.w = gate * vv.w;
    *(float4*)&out[(size_t)r * HID + d] = o;
}

// ---------------------------------------------------------------------------
// Launch
// ---------------------------------------------------------------------------
extern "C" void kernel_launch(void* const* d_in, const int* in_sizes, int n_in,
                              void* d_out, int out_size) {
    const float* hidden = (const float*)d_in[0];
    const int*   hash   = (const int*)d_in[1];
    const float* tab    = (const float*)d_in[2];
    const float* convw  = (const float*)d_in[3];
    const float* scw    = (const float*)d_in[4];
    const float* vw     = (const float*)d_in[5];
    const float* vb     = (const float*)d_in[6];
    const float* kw     = (const float*)d_in[7];
    const float* kb     = (const float*)d_in[8];
    const float* n1     = (const float*)d_in[9];
    const float* n2     = (const float*)d_in[10];
    float* out = (float*)d_out;

    float *A, *val, *keys, *vwt, *kwt;
    cudaGetSymbolAddress((void**)&A,    g_A);
    cudaGetSymbolAddress((void**)&val,  g_value);
    cudaGetSymbolAddress((void**)&keys, g_keys);
    cudaGetSymbolAddress((void**)&vwt,  g_vwt);
    cudaGetSymbolAddress((void**)&kwt,  g_kwt);

    cudaFuncSetAttribute(gemm_tf32, cudaFuncAttributeMaxDynamicSharedMemorySize, TFB_SMEM);

    gather_k<<<BT, 256>>>(hash, tab, A);
    wround_k<<<(EMB * HID / 4 + 255) / 256, 256>>>(vw, vwt, EMB * HID / 4);
    wround_k<<<(CCH * HID / 4 + 255) / 256, 256>>>(kw, kwt, CCH * HID / 4);

    dim3 gv(EMB / 256, BT / 128);
    gemm_tf32<<<gv, 256, TFB_SMEM>>>(A, vwt, vb, val, EMB);

    dim3 gk(CCH / 256, BT / 128);
    gemm_tf32<<<gk, 256, TFB_SMEM>>>(A, kwt, kb, keys, CCH);

    final_k<<<BT * GDIM, 256>>>(hidden, scw, convw, keys, val, n1, n2, out);
}